// round 1
// baseline (speedup 1.0000x reference)
#include <cuda_runtime.h>
#include <math.h>

// Problem constants (ScaledDotProductAttention: B=2, H=12, S=2048, D=64, fp32, causal)
constexpr int Bc = 2;
constexpr int Hc = 12;
constexpr int Sc = 2048;
constexpr int Dc = 64;

constexpr int BM = 128;      // query rows per CTA (one per thread)
constexpr int BN = 64;       // key/value tile size
constexpr int GROUP = 8;     // keys per online-softmax group
constexpr int NTHREADS = 128;

__global__ __launch_bounds__(NTHREADS, 2)
void fa_causal_kernel(const float* __restrict__ Q,
                      const float* __restrict__ K,
                      const float* __restrict__ V,
                      float* __restrict__ O) {
    __shared__ float Ks[BN * Dc];
    __shared__ float Vs[BN * Dc];

    const int head = blockIdx.y;                       // 0 .. B*H-1
    const int m0 = (gridDim.x - 1 - blockIdx.x) * BM;  // reverse order: heavy tiles first
    const int row = m0 + threadIdx.x;
    const size_t head_off = (size_t)head * Sc * Dc;

    // Load this thread's query row into registers, pre-scaled by 1/sqrt(D) * log2(e)
    constexpr float SCALE = 0.125f * 1.4426950408889634f;
    float qr[Dc];
    {
        const float4* q4 = reinterpret_cast<const float4*>(Q + head_off + (size_t)row * Dc);
        #pragma unroll
        for (int i = 0; i < Dc / 4; ++i) {
            float4 t = q4[i];
            qr[4 * i + 0] = t.x * SCALE;
            qr[4 * i + 1] = t.y * SCALE;
            qr[4 * i + 2] = t.z * SCALE;
            qr[4 * i + 3] = t.w * SCALE;
        }
    }

    float acc[Dc];
    #pragma unroll
    for (int i = 0; i < Dc; ++i) acc[i] = 0.0f;
    float mrun = -INFINITY;
    float lrun = 0.0f;

    const int tiles_end = m0 + BM;  // causal: keys < m0+BM are all we need
    for (int j0 = 0; j0 < tiles_end; j0 += BN) {
        // ---- cooperative K/V tile load (coalesced float4) ----
        {
            const float4* kg = reinterpret_cast<const float4*>(K + head_off + (size_t)j0 * Dc);
            const float4* vg = reinterpret_cast<const float4*>(V + head_off + (size_t)j0 * Dc);
            float4* ks4 = reinterpret_cast<float4*>(Ks);
            float4* vs4 = reinterpret_cast<float4*>(Vs);
            #pragma unroll
            for (int i = 0; i < (BN * Dc / 4) / NTHREADS; ++i) {
                int idx = threadIdx.x + i * NTHREADS;
                ks4[idx] = kg[idx];
                vs4[idx] = vg[idx];
            }
        }
        __syncthreads();

        // ---- process tile in groups of GROUP keys (thread-local online softmax) ----
        for (int g = 0; g < BN; g += GROUP) {
            float s[GROUP];
            #pragma unroll
            for (int j = 0; j < GROUP; ++j) s[j] = 0.0f;

            // QK^T: GROUP independent dot-product chains for ILP
            #pragma unroll
            for (int d4 = 0; d4 < Dc / 4; ++d4) {
                const float qx = qr[4 * d4 + 0];
                const float qy = qr[4 * d4 + 1];
                const float qz = qr[4 * d4 + 2];
                const float qw = qr[4 * d4 + 3];
                #pragma unroll
                for (int j = 0; j < GROUP; ++j) {
                    float4 kv = reinterpret_cast<const float4*>(Ks + (g + j) * Dc)[d4];
                    s[j] = fmaf(qx, kv.x, s[j]);
                    s[j] = fmaf(qy, kv.y, s[j]);
                    s[j] = fmaf(qz, kv.z, s[j]);
                    s[j] = fmaf(qw, kv.w, s[j]);
                }
            }

            // causal mask + group max
            float gm = -INFINITY;
            #pragma unroll
            for (int j = 0; j < GROUP; ++j) {
                int jg = j0 + g + j;
                s[j] = (jg <= row) ? s[j] : -INFINITY;
                gm = fmaxf(gm, s[j]);
            }

            // rescale accumulators only if the running max grew
            if (gm > mrun) {
                float f = exp2f(mrun - gm);  // exp2(-inf) = 0 handles first group
                mrun = gm;
                lrun *= f;
                #pragma unroll
                for (int i = 0; i < Dc; ++i) acc[i] *= f;
            }

            // P·V accumulation
            #pragma unroll
            for (int j = 0; j < GROUP; ++j) {
                float p = exp2f(s[j] - mrun);  // masked: exp2(-inf) = 0
                lrun += p;
                #pragma unroll
                for (int d4 = 0; d4 < Dc / 4; ++d4) {
                    float4 vv = reinterpret_cast<const float4*>(Vs + (g + j) * Dc)[d4];
                    acc[4 * d4 + 0] = fmaf(p, vv.x, acc[4 * d4 + 0]);
                    acc[4 * d4 + 1] = fmaf(p, vv.y, acc[4 * d4 + 1]);
                    acc[4 * d4 + 2] = fmaf(p, vv.z, acc[4 * d4 + 2]);
                    acc[4 * d4 + 3] = fmaf(p, vv.w, acc[4 * d4 + 3]);
                }
            }
        }
        __syncthreads();
    }

    // ---- epilogue: normalize and store ----
    const float inv = 1.0f / lrun;
    float4* o4 = reinterpret_cast<float4*>(O + head_off + (size_t)row * Dc);
    #pragma unroll
    for (int i = 0; i < Dc / 4; ++i) {
        o4[i] = make_float4(acc[4 * i + 0] * inv, acc[4 * i + 1] * inv,
                            acc[4 * i + 2] * inv, acc[4 * i + 3] * inv);
    }
}

extern "C" void kernel_launch(void* const* d_in, const int* in_sizes, int n_in,
                              void* d_out, int out_size) {
    const float* q = (const float*)d_in[0];
    const float* k = (const float*)d_in[1];
    const float* v = (const float*)d_in[2];
    // d_in[3] is the causal mask; its direction logic statically resolves to tril-keep,
    // which the kernel implements directly.
    float* o = (float*)d_out;

    dim3 grid(Sc / BM, Bc * Hc);
    fa_causal_kernel<<<grid, NTHREADS>>>(q, k, v, o);
}

// round 6
// speedup vs baseline: 3.8372x; 3.8372x over previous
#include <cuda_runtime.h>
#include <cuda_fp16.h>
#include <cstdint>

constexpr int Sc = 2048, Dc = 64;
constexpr int BM = 128, BN = 64, NT = 256;
constexpr int STR = 72;  // halves per smem row (144B: +16B skew -> conflict-free ldmatrix)

// smem layout (half offsets)
constexpr int QHI = 0, QLO = 9216, KHI = 18432, KLO = 23040, VHI = 27648, VLO = 32256;
constexpr int SMEM_BYTES = 36864 * 2;  // 73728

#define DI __device__ __forceinline__

DI uint32_t h2u(__half2 h) { return *reinterpret_cast<uint32_t*>(&h); }

DI void mma16816(float* c, const uint32_t* a, const uint32_t* b) {
    asm volatile(
        "mma.sync.aligned.m16n8k16.row.col.f32.f16.f16.f32 "
        "{%0,%1,%2,%3}, {%4,%5,%6,%7}, {%8,%9}, {%0,%1,%2,%3};"
        : "+f"(c[0]), "+f"(c[1]), "+f"(c[2]), "+f"(c[3])
        : "r"(a[0]), "r"(a[1]), "r"(a[2]), "r"(a[3]), "r"(b[0]), "r"(b[1]));
}
DI void ldsm4(uint32_t* r, uint32_t a) {
    asm volatile("ldmatrix.sync.aligned.m8n8.x4.shared.b16 {%0,%1,%2,%3}, [%4];"
                 : "=r"(r[0]), "=r"(r[1]), "=r"(r[2]), "=r"(r[3]) : "r"(a));
}
DI void ldsm4t(uint32_t* r, uint32_t a) {
    asm volatile("ldmatrix.sync.aligned.m8n8.x4.trans.shared.b16 {%0,%1,%2,%3}, [%4];"
                 : "=r"(r[0]), "=r"(r[1]), "=r"(r[2]), "=r"(r[3]) : "r"(a));
}
DI float ex2(float x) { float y; asm("ex2.approx.ftz.f32 %0, %1;" : "=f"(y) : "f"(x)); return y; }

__global__ __launch_bounds__(NT, 2)
void fa_mma_kernel(const float* __restrict__ Q, const float* __restrict__ K,
                   const float* __restrict__ V, float* __restrict__ O) {
    extern __shared__ __half sm[];
    const int tid = threadIdx.x;
    const int lane = tid & 31, w = tid >> 5;
    const int r8 = lane & 7, g = lane >> 3;          // ldmatrix lane decomposition
    const int q4 = lane & 3, rr = lane >> 2;         // mma C-fragment decomposition
    const int head = blockIdx.y;
    const int m0 = (int)(gridDim.x - 1 - blockIdx.x) * BM;  // heavy tiles first
    const size_t hoff = (size_t)head * Sc * Dc;

    const uint32_t sb = (uint32_t)__cvta_generic_to_shared(sm);
    // ldmatrix base addresses (byte offsets)
    // A (Q, non-trans): m0..3 = rows{0-7,8-15} x k{0-7,8-15}
    const uint32_t aq = sb + (uint32_t)(QHI + (16 * w + r8 + (g & 1) * 8) * STR + (g >> 1) * 8) * 2;
    // B for QK (K, NON-trans): m0..3 = keys{0-7}xd{0-7}, keys{0-7}xd{8-15}, keys{8-15}xd{0-7}, keys{8-15}xd{8-15}
    const uint32_t kb = sb + (uint32_t)(KHI + (r8 + ((g >> 1) & 1) * 8) * STR + (g & 1) * 8) * 2;
    // B for PV (V, trans): m0..3 = keys{0-7}xd{0-7}, keys{8-15}xd{0-7}, keys{0-7}xd{8-15}, keys{8-15}xd{8-15}
    const uint32_t vb = sb + (uint32_t)(VHI + (r8 + (g & 1) * 8) * STR + (g >> 1) * 8) * 2;

    // ---- Q: load, scale, split hi/lo into smem (once) ----
    constexpr float SC = 0.125f * 1.4426950408889634f;  // 1/sqrt(64) * log2(e)
#pragma unroll
    for (int i = 0; i < 8; ++i) {
        int idx = tid + NT * i;                 // 0..2047
        int row = idx >> 4, dg = idx & 15;      // d = 4*dg
        float4 t = reinterpret_cast<const float4*>(Q + hoff + (size_t)(m0 + row) * Dc)[dg];
        t.x *= SC; t.y *= SC; t.z *= SC; t.w *= SC;
        __half2 h0 = __floats2half2_rn(t.x, t.y), h1 = __floats2half2_rn(t.z, t.w);
        __half2 l0 = __floats2half2_rn(t.x - __low2float(h0), t.y - __high2float(h0));
        __half2 l1 = __floats2half2_rn(t.z - __low2float(h1), t.w - __high2float(h1));
        __half2* ph = reinterpret_cast<__half2*>(sm + QHI + row * STR + 4 * dg);
        __half2* pl = reinterpret_cast<__half2*>(sm + QLO + row * STR + 4 * dg);
        ph[0] = h0; ph[1] = h1; pl[0] = l0; pl[1] = l1;
    }

    float oc[8][4];
#pragma unroll
    for (int j = 0; j < 8; ++j)
#pragma unroll
        for (int c = 0; c < 4; ++c) oc[j][c] = 0.0f;
    float mr0 = -1e30f, mr1 = -1e30f, lr0 = 0.0f, lr1 = 0.0f;

    const int row0 = m0 + 16 * w + rr, row1 = row0 + 8;

    for (int j0 = 0; j0 < m0 + BM; j0 += BN) {
        // ---- K/V tile: fp32 -> fp16 hi/lo into smem ----
        __syncthreads();
#pragma unroll
        for (int i = 0; i < 4; ++i) {
            int idx = tid + NT * i;             // 0..1023
            int key = idx >> 4, dg = idx & 15;
            float4 t = reinterpret_cast<const float4*>(K + hoff + (size_t)(j0 + key) * Dc)[dg];
            __half2 h0 = __floats2half2_rn(t.x, t.y), h1 = __floats2half2_rn(t.z, t.w);
            __half2 l0 = __floats2half2_rn(t.x - __low2float(h0), t.y - __high2float(h0));
            __half2 l1 = __floats2half2_rn(t.z - __low2float(h1), t.w - __high2float(h1));
            __half2* ph = reinterpret_cast<__half2*>(sm + KHI + key * STR + 4 * dg);
            __half2* pl = reinterpret_cast<__half2*>(sm + KLO + key * STR + 4 * dg);
            ph[0] = h0; ph[1] = h1; pl[0] = l0; pl[1] = l1;

            float4 u = reinterpret_cast<const float4*>(V + hoff + (size_t)(j0 + key) * Dc)[dg];
            __half2 vh0 = __floats2half2_rn(u.x, u.y), vh1 = __floats2half2_rn(u.z, u.w);
            __half2 vl0 = __floats2half2_rn(u.x - __low2float(vh0), u.y - __high2float(vh0));
            __half2 vl1 = __floats2half2_rn(u.z - __low2float(vh1), u.w - __high2float(vh1));
            __half2* qh = reinterpret_cast<__half2*>(sm + VHI + key * STR + 4 * dg);
            __half2* ql = reinterpret_cast<__half2*>(sm + VLO + key * STR + 4 * dg);
            qh[0] = vh0; qh[1] = vh1; ql[0] = vl0; ql[1] = vl1;
        }
        __syncthreads();

        // ---- S = Qhi*Khi + Qhi*Klo + Qlo*Khi ----
        float sc[8][4];
#pragma unroll
        for (int j = 0; j < 8; ++j)
#pragma unroll
            for (int c = 0; c < 4; ++c) sc[j][c] = 0.0f;

#pragma unroll
        for (int t = 0; t < 4; ++t) {
            uint32_t ah[4], al[4];
            ldsm4(ah, aq + t * 32);
            ldsm4(al, aq + t * 32 + (QLO - QHI) * 2);
#pragma unroll
            for (int u = 0; u < 4; ++u) {
                uint32_t bh[4], bl[4];
                ldsm4(bh, kb + u * 2304 + t * 32);      // NON-trans: K rows give B[k][n] packed in k
                ldsm4(bl, kb + u * 2304 + t * 32 + (KLO - KHI) * 2);
                mma16816(sc[2 * u],     ah, bh);
                mma16816(sc[2 * u + 1], ah, bh + 2);
                mma16816(sc[2 * u],     ah, bl);
                mma16816(sc[2 * u + 1], ah, bl + 2);
                mma16816(sc[2 * u],     al, bh);
                mma16816(sc[2 * u + 1], al, bh + 2);
            }
        }

        // ---- online softmax (rows row0, row1; cols spread over quad lanes) ----
        if (j0 + BN - 1 > m0) {  // diagonal tile: causal mask
            const int col0 = j0 + 2 * q4;
#pragma unroll
            for (int j = 0; j < 8; ++j) {
                int c0 = col0 + 8 * j;
                sc[j][0] = (c0     <= row0) ? sc[j][0] : -1e30f;
                sc[j][1] = (c0 + 1 <= row0) ? sc[j][1] : -1e30f;
                sc[j][2] = (c0     <= row1) ? sc[j][2] : -1e30f;
                sc[j][3] = (c0 + 1 <= row1) ? sc[j][3] : -1e30f;
            }
        }
        float mx0 = -1e30f, mx1 = -1e30f;
#pragma unroll
        for (int j = 0; j < 8; ++j) {
            mx0 = fmaxf(mx0, fmaxf(sc[j][0], sc[j][1]));
            mx1 = fmaxf(mx1, fmaxf(sc[j][2], sc[j][3]));
        }
        mx0 = fmaxf(mx0, __shfl_xor_sync(0xffffffffu, mx0, 1));
        mx0 = fmaxf(mx0, __shfl_xor_sync(0xffffffffu, mx0, 2));
        mx1 = fmaxf(mx1, __shfl_xor_sync(0xffffffffu, mx1, 1));
        mx1 = fmaxf(mx1, __shfl_xor_sync(0xffffffffu, mx1, 2));
        const float mn0 = fmaxf(mr0, mx0), mn1 = fmaxf(mr1, mx1);
        const float al0 = ex2(mr0 - mn0), al1 = ex2(mr1 - mn1);
        mr0 = mn0; mr1 = mn1;

        float s0 = 0.0f, s1 = 0.0f;
#pragma unroll
        for (int j = 0; j < 8; ++j) {
            sc[j][0] = ex2(sc[j][0] - mn0); s0 += sc[j][0];
            sc[j][1] = ex2(sc[j][1] - mn0); s0 += sc[j][1];
            sc[j][2] = ex2(sc[j][2] - mn1); s1 += sc[j][2];
            sc[j][3] = ex2(sc[j][3] - mn1); s1 += sc[j][3];
        }
        s0 += __shfl_xor_sync(0xffffffffu, s0, 1);
        s0 += __shfl_xor_sync(0xffffffffu, s0, 2);
        s1 += __shfl_xor_sync(0xffffffffu, s1, 1);
        s1 += __shfl_xor_sync(0xffffffffu, s1, 2);
        lr0 = lr0 * al0 + s0;
        lr1 = lr1 * al1 + s1;

        // rescale O accumulators
#pragma unroll
        for (int j = 0; j < 8; ++j) {
            oc[j][0] *= al0; oc[j][1] *= al0;
            oc[j][2] *= al1; oc[j][3] *= al1;
        }

        // ---- O += Phi*Vhi + Phi*Vlo + Plo*Vhi ----
#pragma unroll
        for (int t = 0; t < 4; ++t) {
            uint32_t ph[4], pl[4];
            {
                __half2 h, l;
                h = __floats2half2_rn(sc[2 * t][0], sc[2 * t][1]);
                l = __floats2half2_rn(sc[2 * t][0] - __low2float(h), sc[2 * t][1] - __high2float(h));
                ph[0] = h2u(h); pl[0] = h2u(l);
                h = __floats2half2_rn(sc[2 * t][2], sc[2 * t][3]);
                l = __floats2half2_rn(sc[2 * t][2] - __low2float(h), sc[2 * t][3] - __high2float(h));
                ph[1] = h2u(h); pl[1] = h2u(l);
                h = __floats2half2_rn(sc[2 * t + 1][0], sc[2 * t + 1][1]);
                l = __floats2half2_rn(sc[2 * t + 1][0] - __low2float(h), sc[2 * t + 1][1] - __high2float(h));
                ph[2] = h2u(h); pl[2] = h2u(l);
                h = __floats2half2_rn(sc[2 * t + 1][2], sc[2 * t + 1][3]);
                l = __floats2half2_rn(sc[2 * t + 1][2] - __low2float(h), sc[2 * t + 1][3] - __high2float(h));
                ph[3] = h2u(h); pl[3] = h2u(l);
            }
#pragma unroll
            for (int j = 0; j < 8; j += 2) {
                uint32_t vh[4], vl[4];
                ldsm4t(vh, vb + t * 2304 + j * 16);      // trans: V rows (=k) -> B[k][n] packed in k
                ldsm4t(vl, vb + t * 2304 + j * 16 + (VLO - VHI) * 2);
                mma16816(oc[j],     ph, vh);
                mma16816(oc[j + 1], ph, vh + 2);
                mma16816(oc[j],     ph, vl);
                mma16816(oc[j + 1], ph, vl + 2);
                mma16816(oc[j],     pl, vh);
                mma16816(oc[j + 1], pl, vh + 2);
            }
        }
    }

    // ---- epilogue ----
    const float i0 = 1.0f / lr0, i1 = 1.0f / lr1;
#pragma unroll
    for (int j = 0; j < 8; ++j) {
        int col = 8 * j + 2 * q4;
        reinterpret_cast<float2*>(O + hoff + (size_t)row0 * Dc + col)[0] =
            make_float2(oc[j][0] * i0, oc[j][1] * i0);
        reinterpret_cast<float2*>(O + hoff + (size_t)row1 * Dc + col)[0] =
            make_float2(oc[j][2] * i1, oc[j][3] * i1);
    }
}

extern "C" void kernel_launch(void* const* d_in, const int* in_sizes, int n_in,
                              void* d_out, int out_size) {
    const float* q = (const float*)d_in[0];
    const float* k = (const float*)d_in[1];
    const float* v = (const float*)d_in[2];
    float* o = (float*)d_out;

    cudaFuncSetAttribute(fa_mma_kernel, cudaFuncAttributeMaxDynamicSharedMemorySize, SMEM_BYTES);
    dim3 grid(Sc / BM, 2 * 12);
    fa_mma_kernel<<<grid, NT, SMEM_BYTES>>>(q, k, v, o);
}